// round 4
// baseline (speedup 1.0000x reference)
#include <cuda_runtime.h>
#include <math.h>

#define KCODES   8192
#define DIM      256
#define NTOK     8192       // B*H*W
#define HWSZ     1024
#define ZQ_ELEMS 2097152
#define OUT_FULL (ZQ_ELEMS + 2 + NTOK)
#define CAP      256

static __device__ float    g_w2[KCODES];
static __device__ unsigned g_wmax2_bits;     // monotone max, idempotent across replays
static __device__ int      g_idx[NTOK];
static __device__ int      g_hist[KCODES];
static __device__ double   g_loss;
static __device__ unsigned g_done;

// ============ Kernel A: per-code norms + zero scratch (no transpose!) =========
__global__ void __launch_bounds__(256) k_prep(const float* __restrict__ w) {
    int blk = blockIdx.x, t = threadIdx.x;
    if (blk < 1024) {
        int row  = (blk << 3) | (t >> 5);     // one warp per codebook row
        int lane = t & 31;
        const float4* p = (const float4*)(w + (size_t)row * DIM);
        float s = 0.f;
#pragma unroll
        for (int j = 0; j < 2; j++) {
            float4 v = __ldg(p + lane * 2 + j);
            s += v.x * v.x + v.y * v.y + v.z * v.z + v.w * v.w;
        }
#pragma unroll
        for (int o = 16; o; o >>= 1) s += __shfl_xor_sync(0xffffffffu, s, o);
        if (lane == 0) {
            g_w2[row] = s;
            atomicMax(&g_wmax2_bits, __float_as_uint(s));
        }
    } else {
        int i = ((blk - 1024) << 8) | t;
        g_hist[i] = 0;
        if (i == 0) { g_loss = 0.0; g_done = 0u; }
    }
}

// ======= Kernel B: argmax(gumbel + 2 z.w - |w|^2), smem-staged gumbel ========
__global__ void __launch_bounds__(256, 6) k_argmax(const float* __restrict__ gum,
                                                   const float* __restrict__ ze,
                                                   const float* __restrict__ w,
                                                   float* __restrict__ out,
                                                   int write_extras) {
    const int n = blockIdx.x;
    const int t = threadIdx.x;
    const int lane = t & 31, wrp = t >> 5;
    const int b = n >> 10, hw = n & (HWSZ - 1);

    __shared__ float4 sg4[KCODES / 4];      // 32KB: full gumbel row
    __shared__ float  sh_z[DIM];
    __shared__ float  sh_red[8];
    __shared__ float  sh_m[8];
    __shared__ int    sh_cand[CAP];
    __shared__ float  sh_cg[CAP];
    __shared__ int    sh_cnt;
    __shared__ float  sh_bv[8];
    __shared__ int    sh_bk[8];

    // z row read directly from NCHW (strided; 32B sectors shared by 8 blocks -> L2-amortized)
    float zv = __ldg(&ze[(size_t)(b * DIM + t) * HWSZ + hw]);
    if (t == 0) sh_cnt = 0;

    // single streaming pass over gumbel: stage to smem + running max
    const float4* row4 = (const float4*)(gum + (size_t)n * KCODES);
    float m = -INFINITY;
#pragma unroll
    for (int j = 0; j < 8; j++) {
        float4 v = __ldcs(row4 + t + j * 256);
        sg4[t + j * 256] = v;
        m = fmaxf(m, fmaxf(fmaxf(v.x, v.y), fmaxf(v.z, v.w)));
    }
    sh_z[t] = zv;
    float s = zv * zv;
#pragma unroll
    for (int o = 16; o; o >>= 1) {
        s += __shfl_xor_sync(0xffffffffu, s, o);
        m = fmaxf(m, __shfl_xor_sync(0xffffffffu, m, o));
    }
    if (lane == 0) { sh_red[wrp] = s; sh_m[wrp] = m; }
    __syncthreads();
    float zn2 = 0.f, gmax = -INFINITY;
#pragma unroll
    for (int i = 0; i < 8; i++) { zn2 += sh_red[i]; gmax = fmaxf(gmax, sh_m[i]); }
    float wmax2  = __uint_as_float(g_wmax2_bits);
    float thresh = gmax - (4.f * sqrtf(zn2) * sqrtf(wmax2) + wmax2 + 1e-5f);

    // collect candidates from smem copy
#pragma unroll
    for (int j = 0; j < 8; j++) {
        float4 v = sg4[t + j * 256];
        int kb = (t + j * 256) << 2;
        if (v.x >= thresh) { int p = atomicAdd(&sh_cnt, 1); if (p < CAP) { sh_cand[p] = kb;     sh_cg[p] = v.x; } }
        if (v.y >= thresh) { int p = atomicAdd(&sh_cnt, 1); if (p < CAP) { sh_cand[p] = kb + 1; sh_cg[p] = v.y; } }
        if (v.z >= thresh) { int p = atomicAdd(&sh_cnt, 1); if (p < CAP) { sh_cand[p] = kb + 2; sh_cg[p] = v.z; } }
        if (v.w >= thresh) { int p = atomicAdd(&sh_cnt, 1); if (p < CAP) { sh_cand[p] = kb + 3; sh_cg[p] = v.w; } }
    }
    __syncthreads();
    int cnt = sh_cnt;
    int best_k = -1;

    if (cnt == 1) {
        best_k = sh_cand[0];                           // ~87% of tokens
    } else if (cnt <= CAP) {
        // warp-parallel exact scoring: warp handles candidates wrp, wrp+8, ...
        float bv = -INFINITY; int bk = KCODES;
        for (int c = wrp; c < cnt; c += 8) {
            int k = sh_cand[c];
            const float4* wr = (const float4*)(w + (size_t)k * DIM);
            float dot = 0.f;
#pragma unroll
            for (int j = 0; j < 2; j++) {
                float4 a = __ldg(wr + lane * 2 + j);
                int db = lane * 8 + j * 4;
                dot += a.x * sh_z[db] + a.y * sh_z[db + 1] + a.z * sh_z[db + 2] + a.w * sh_z[db + 3];
            }
#pragma unroll
            for (int o = 16; o; o >>= 1) dot += __shfl_xor_sync(0xffffffffu, dot, o);
            float sc = sh_cg[c] + 2.f * dot - g_w2[k];
            if (sc > bv || (sc == bv && k < bk)) { bv = sc; bk = k; }
        }
        if (lane == 0) { sh_bv[wrp] = bv; sh_bk[wrp] = bk; }
        __syncthreads();
        if (t == 0) {
            float fb = -INFINITY; int fk = KCODES;
#pragma unroll
            for (int i = 0; i < 8; i++) {
                float v = sh_bv[i]; int k = sh_bk[i];
                if (v > fb || (v == fb && k < fk)) { fb = v; fk = k; }
            }
            best_k = fk;
        }
    } else {
        // statistically unreachable safety net: exact full scan (gumbel from smem)
        const float* sgf = (const float*)sg4;
        float bs = -INFINITY; int bk = KCODES;
        for (int k = t; k < KCODES; k += 256) {
            float dot = 0.f;
            for (int d = 0; d < DIM; d++) dot += sh_z[d] * w[(size_t)k * DIM + d];
            float sc = sgf[k] + 2.f * dot - g_w2[k];
            if (sc > bs || (sc == bs && k < bk)) { bs = sc; bk = k; }
        }
        __syncthreads();
        sh_cg[t] = bs; sh_cand[t] = bk;
        __syncthreads();
        for (int off = 128; off; off >>= 1) {
            if (t < off) {
                float ov = sh_cg[t + off]; int ok = sh_cand[t + off];
                if (ov > sh_cg[t] || (ov == sh_cg[t] && ok < sh_cand[t])) { sh_cg[t] = ov; sh_cand[t] = ok; }
            }
            __syncthreads();
        }
        best_k = sh_cand[0];
    }

    if (t == 0) {
        g_idx[n] = best_k;
        atomicAdd(&g_hist[best_k], 1);
        if (write_extras) out[ZQ_ELEMS + 2 + n] = (float)best_k;
    }
}

// ==== Kernel C: coalesced gather + STE write + loss + (last block) scalars ====
__global__ void __launch_bounds__(256) k_out(const float* __restrict__ ze,
                                             const float* __restrict__ w,
                                             float* __restrict__ out,
                                             int write_extras) {
    __shared__ float tile[32][33];
    __shared__ int   kk[32];
    __shared__ float sr[8];
    __shared__ int   s_last;
    int blk = blockIdx.x, t = threadIdx.x;
    int tx = t & 31, ty = t >> 5;
    int b = blk >> 8, rem = blk & 255;
    int d0 = (rem >> 5) << 5;
    int hw0 = (rem & 31) << 5;

    if (t < 32) kk[t] = g_idx[b * HWSZ + hw0 + t];
    __syncthreads();
#pragma unroll
    for (int i = 0; i < 4; i++) {
        int tok = ty + i * 8;
        tile[tok][tx] = __ldg(&w[(size_t)kk[tok] * DIM + d0 + tx]);
    }
    __syncthreads();

    float acc = 0.f;
#pragma unroll
    for (int i = 0; i < 4; i++) {
        int dd = ty + i * 8;
        size_t gi = (size_t)(b * DIM + d0 + dd) * HWSZ + hw0 + tx;  // NCHW, coalesced
        float zq  = tile[tx][dd];
        float zev = ze[gi];
        float df  = zq - zev;
        out[gi]   = zev + df;
        acc += df * df;
    }
#pragma unroll
    for (int o = 16; o; o >>= 1) acc += __shfl_xor_sync(0xffffffffu, acc, o);
    if ((t & 31) == 0) sr[t >> 5] = acc;
    __syncthreads();
    if (t == 0) {
        float tot = 0.f;
#pragma unroll
        for (int q = 0; q < 8; q++) tot += sr[q];
        atomicAdd(&g_loss, (double)tot);
        __threadfence();
        unsigned old = atomicAdd(&g_done, 1u);
        s_last = (old == gridDim.x - 1) ? 1 : 0;
    }
    __syncthreads();

    if (s_last && write_extras) {
        double accp = 0.0;
        for (int k = t; k < KCODES; k += 256) {
            float p = (float)g_hist[k] * (1.0f / (float)NTOK);
            accp += (double)(p * logf(p + 1e-10f));
        }
#pragma unroll
        for (int o = 16; o; o >>= 1) accp += __shfl_xor_sync(0xffffffffu, accp, o);
        __shared__ double dr[8];
        if ((t & 31) == 0) dr[t >> 5] = accp;
        __syncthreads();
        if (t == 0) {
            double tot = 0.0;
#pragma unroll
            for (int q = 0; q < 8; q++) tot += dr[q];
            double loss = *((volatile double*)&g_loss);
            out[ZQ_ELEMS]     = (float)(1.25 * loss / (double)ZQ_ELEMS);
            out[ZQ_ELEMS + 1] = (float)exp(-tot);
        }
    }
}

extern "C" void kernel_launch(void* const* d_in, const int* in_sizes, int n_in,
                              void* d_out, int out_size) {
    const float* gum = nullptr;
    const float* small[2] = {nullptr, nullptr};
    int ns = 0;
    for (int i = 0; i < n_in; i++) {
        if (in_sizes[i] == KCODES * NTOK) gum = (const float*)d_in[i];
        else if (ns < 2) small[ns++] = (const float*)d_in[i];
    }
    const float* z_e = small[0];
    const float* w   = small[1];
    float* out = (float*)d_out;
    int write_extras = (out_size >= OUT_FULL) ? 1 : 0;

    k_prep<<<1056, 256>>>(w);
    k_argmax<<<NTOK, 256>>>(gum, z_e, w, out, write_extras);
    k_out<<<2048, 256>>>(z_e, w, out, write_extras);
}

// round 7
// speedup vs baseline: 1.4020x; 1.4020x over previous
#include <cuda_runtime.h>
#include <math.h>

#define KCODES   8192
#define DIM      256
#define NTOK     8192       // B*H*W
#define HWSZ     1024
#define ZQ_ELEMS 2097152
#define OUT_FULL (ZQ_ELEMS + 2 + NTOK)
#define CAP      256
#define AT       512        // argmax block size

static __device__ float    g_flat[NTOK * DIM];   // z_e transposed to [N, D]
static __device__ float    g_w2[KCODES];
static __device__ unsigned g_wmax2_bits;         // monotone max, idempotent across replays
static __device__ int      g_idx[NTOK];
static __device__ int      g_hist[KCODES];
static __device__ double   g_loss;
static __device__ unsigned g_done;

// ===== Kernel A: transpose (32d x 64hw tiles) + per-code norms + zeroing =====
__global__ void __launch_bounds__(256) k_prep(const float* __restrict__ ze,
                                              const float* __restrict__ w) {
    int blk = blockIdx.x, t = threadIdx.x;
    if (blk < 1024) {
        // transpose z_e [B,D,HW] -> g_flat [B*HW, D]; tile = 32 d x 64 hw
        __shared__ float tile[32][65];
        int b = blk >> 7, rem = blk & 127;
        int d0 = (rem >> 4) << 5;
        int hw0 = (rem & 15) << 6;
        int col = t & 63, r4 = t >> 6;        // load: 4 d-rows per iter
#pragma unroll
        for (int i = 0; i < 8; i++) {
            int d = r4 + i * 4;
            tile[d][col] = __ldg(&ze[(size_t)(b * DIM + d0 + d) * HWSZ + hw0 + col]);
        }
        __syncthreads();
        int dl = t & 31, tw = t >> 5;         // store: 8 tokens per iter
#pragma unroll
        for (int i = 0; i < 8; i++) {
            int tok = tw + i * 8;
            g_flat[(size_t)(b * HWSZ + hw0 + tok) * DIM + d0 + dl] = tile[dl][tok];
        }
    } else if (blk < 2048) {
        // |w_k|^2 (one warp per row) + global max
        int row  = ((blk - 1024) << 3) | (t >> 5);
        int lane = t & 31;
        const float4* p = (const float4*)(w + (size_t)row * DIM);
        float s = 0.f;
#pragma unroll
        for (int j = 0; j < 2; j++) {
            float4 v = __ldg(p + lane * 2 + j);
            s += v.x * v.x + v.y * v.y + v.z * v.z + v.w * v.w;
        }
#pragma unroll
        for (int o = 16; o; o >>= 1) s += __shfl_xor_sync(0xffffffffu, s, o);
        if (lane == 0) {
            g_w2[row] = s;
            atomicMax(&g_wmax2_bits, __float_as_uint(s));
        }
    } else {
        int i = ((blk - 2048) << 8) | t;
        g_hist[i] = 0;
        if (i == 0) { g_loss = 0.0; g_done = 0u; }
    }
}

// ==== Kernel B: argmax(gumbel + 2 z.w - |w|^2), 512 thr, bounded pruning =====
__global__ void __launch_bounds__(AT, 3) k_argmax(const float* __restrict__ gum,
                                                  const float* __restrict__ w,
                                                  float* __restrict__ out,
                                                  int write_extras) {
    const int n = blockIdx.x;
    const int t = threadIdx.x;
    const int lane = t & 31, wrp = t >> 5;     // 16 warps
    __shared__ float sh_z[DIM];
    __shared__ float sh_red[16];
    __shared__ float sh_m[16];
    __shared__ int   sh_cand[CAP];
    __shared__ float sh_cg[CAP];
    __shared__ int   sh_cnt;
    __shared__ float sh_bv[16];
    __shared__ int   sh_bk[16];
    __shared__ float sh_vs[AT];
    __shared__ int   sh_ks[AT];

    // token's z row (coalesced from g_flat) + |z|^2
    float zv = 0.f;
    if (t < DIM) { zv = g_flat[n * DIM + t]; sh_z[t] = zv; }
    if (t == 0) sh_cnt = 0;

    // single streaming pass over gumbel row; 16 values/thread in registers
    const float4* row4 = (const float4*)(gum + (size_t)n * KCODES);
    float4 vv[4];
#pragma unroll
    for (int j = 0; j < 4; j++) vv[j] = __ldcs(row4 + t + j * AT);
    float m = -INFINITY;
#pragma unroll
    for (int j = 0; j < 4; j++) {
        float4 v = vv[j];
        m = fmaxf(m, fmaxf(fmaxf(v.x, v.y), fmaxf(v.z, v.w)));
    }
    float s = zv * zv;
#pragma unroll
    for (int o = 16; o; o >>= 1) {
        s += __shfl_xor_sync(0xffffffffu, s, o);
        m = fmaxf(m, __shfl_xor_sync(0xffffffffu, m, o));
    }
    if (lane == 0) { sh_red[wrp] = s; sh_m[wrp] = m; }
    __syncthreads();
    float zn2 = 0.f, gmax = -INFINITY;
#pragma unroll
    for (int i = 0; i < 16; i++) { zn2 += sh_red[i]; gmax = fmaxf(gmax, sh_m[i]); }
    float wmax2  = __uint_as_float(g_wmax2_bits);
    float thresh = gmax - (4.f * sqrtf(zn2) * sqrtf(wmax2) + wmax2 + 1e-5f);

    // collect candidates (index + gumbel value) from registers
#pragma unroll
    for (int j = 0; j < 4; j++) {
        float4 v = vv[j];
        int kb = (t + j * AT) << 2;
        if (v.x >= thresh) { int p = atomicAdd(&sh_cnt, 1); if (p < CAP) { sh_cand[p] = kb;     sh_cg[p] = v.x; } }
        if (v.y >= thresh) { int p = atomicAdd(&sh_cnt, 1); if (p < CAP) { sh_cand[p] = kb + 1; sh_cg[p] = v.y; } }
        if (v.z >= thresh) { int p = atomicAdd(&sh_cnt, 1); if (p < CAP) { sh_cand[p] = kb + 2; sh_cg[p] = v.z; } }
        if (v.w >= thresh) { int p = atomicAdd(&sh_cnt, 1); if (p < CAP) { sh_cand[p] = kb + 3; sh_cg[p] = v.w; } }
    }
    __syncthreads();
    int cnt = sh_cnt;
    int best_k = -1;

    if (cnt == 1) {
        best_k = sh_cand[0];                           // ~87% of tokens
    } else if (cnt <= CAP) {
        // warp-parallel exact scoring: warp handles candidates wrp, wrp+16, ...
        float bv = -INFINITY; int bk = KCODES;
        for (int c = wrp; c < cnt; c += 16) {
            int k = sh_cand[c];
            const float4* wr = (const float4*)(w + (size_t)k * DIM);
            float dot = 0.f;
#pragma unroll
            for (int j = 0; j < 2; j++) {
                float4 a = __ldg(wr + lane * 2 + j);
                int db = lane * 8 + j * 4;
                dot += a.x * sh_z[db] + a.y * sh_z[db + 1] + a.z * sh_z[db + 2] + a.w * sh_z[db + 3];
            }
#pragma unroll
            for (int o = 16; o; o >>= 1) dot += __shfl_xor_sync(0xffffffffu, dot, o);
            float sc = sh_cg[c] + 2.f * dot - g_w2[k];
            if (sc > bv || (sc == bv && k < bk)) { bv = sc; bk = k; }
        }
        if (lane == 0) { sh_bv[wrp] = bv; sh_bk[wrp] = bk; }
        __syncthreads();
        if (t == 0) {
            float fb = -INFINITY; int fk = KCODES;
#pragma unroll
            for (int i = 0; i < 16; i++) {
                float v = sh_bv[i]; int k = sh_bk[i];
                if (v > fb || (v == fb && k < fk)) { fb = v; fk = k; }
            }
            best_k = fk;
        }
    } else {
        // statistically unreachable safety net: exact full scan
        float bs = -INFINITY; int bk = KCODES;
        for (int k = t; k < KCODES; k += AT) {
            float dot = 0.f;
            for (int d = 0; d < DIM; d++) dot += sh_z[d] * w[(size_t)k * DIM + d];
            float sc = __ldg(&gum[(size_t)n * KCODES + k]) + 2.f * dot - g_w2[k];
            if (sc > bs || (sc == bs && k < bk)) { bs = sc; bk = k; }
        }
        sh_vs[t] = bs; sh_ks[t] = bk;
        __syncthreads();
        for (int off = AT / 2; off; off >>= 1) {
            if (t < off) {
                float ov = sh_vs[t + off]; int ok = sh_ks[t + off];
                if (ov > sh_vs[t] || (ov == sh_vs[t] && ok < sh_ks[t])) { sh_vs[t] = ov; sh_ks[t] = ok; }
            }
            __syncthreads();
        }
        best_k = sh_ks[0];
    }

    if (t == 0) {
        g_idx[n] = best_k;
        atomicAdd(&g_hist[best_k], 1);
        if (write_extras) out[ZQ_ELEMS + 2 + n] = (float)best_k;
    }
}

// == Kernel C: gather (64-token tiles) + STE write + loss + last-block scalars =
__global__ void __launch_bounds__(256) k_out(const float* __restrict__ ze,
                                             const float* __restrict__ w,
                                             float* __restrict__ out,
                                             int write_extras) {
    __shared__ float tile[64][33];     // [token][dim]
    __shared__ int   kk[64];
    __shared__ float sr[8];
    __shared__ int   s_last;
    int blk = blockIdx.x, t = threadIdx.x;
    int tx = t & 31, tw = t >> 5;
    int b = blk >> 7, rem = blk & 127;
    int d0  = (rem >> 4) << 5;
    int hw0 = (rem & 15) << 6;

    if (t < 64) kk[t] = g_idx[b * HWSZ + hw0 + t];
    __syncthreads();
    // coalesced load of 64 codebook row-slices (32 dims each)
#pragma unroll
    for (int i = 0; i < 8; i++) {
        int tok = tw + i * 8;
        tile[tok][tx] = __ldg(&w[(size_t)kk[tok] * DIM + d0 + tx]);
    }
    __syncthreads();

    float acc = 0.f;
#pragma unroll
    for (int i = 0; i < 4; i++) {
        int dd = tw + i * 8;
#pragma unroll
        for (int h = 0; h < 2; h++) {
            int hwl = h * 32 + tx;
            size_t gi = (size_t)(b * DIM + d0 + dd) * HWSZ + hw0 + hwl;  // NCHW, coalesced
            float zq  = tile[hwl][dd];
            float zev = ze[gi];
            float df  = zq - zev;
            out[gi]   = zev + df;
            acc += df * df;
        }
    }
#pragma unroll
    for (int o = 16; o; o >>= 1) acc += __shfl_xor_sync(0xffffffffu, acc, o);
    if (tx == 0) sr[tw] = acc;
    __syncthreads();
    if (t == 0) {
        float tot = 0.f;
#pragma unroll
        for (int q = 0; q < 8; q++) tot += sr[q];
        atomicAdd(&g_loss, (double)tot);
        __threadfence();
        unsigned old = atomicAdd(&g_done, 1u);
        s_last = (old == gridDim.x - 1) ? 1 : 0;
    }
    __syncthreads();

    if (s_last && write_extras) {
        double accp = 0.0;
        for (int k = t; k < KCODES; k += 256) {
            float p = (float)g_hist[k] * (1.0f / (float)NTOK);
            accp += (double)(p * logf(p + 1e-10f));
        }
#pragma unroll
        for (int o = 16; o; o >>= 1) accp += __shfl_xor_sync(0xffffffffu, accp, o);
        __shared__ double dr[8];
        if ((t & 31) == 0) dr[t >> 5] = accp;
        __syncthreads();
        if (t == 0) {
            double tot = 0.0;
#pragma unroll
            for (int q = 0; q < 8; q++) tot += dr[q];
            double loss = *((volatile double*)&g_loss);
            out[ZQ_ELEMS]     = (float)(1.25 * loss / (double)ZQ_ELEMS);
            out[ZQ_ELEMS + 1] = (float)exp(-tot);
        }
    }
}

extern "C" void kernel_launch(void* const* d_in, const int* in_sizes, int n_in,
                              void* d_out, int out_size) {
    const float* gum = nullptr;
    const float* small[2] = {nullptr, nullptr};
    int ns = 0;
    for (int i = 0; i < n_in; i++) {
        if (in_sizes[i] == KCODES * NTOK) gum = (const float*)d_in[i];
        else if (ns < 2) small[ns++] = (const float*)d_in[i];
    }
    const float* z_e = small[0];
    const float* w   = small[1];
    float* out = (float*)d_out;
    int write_extras = (out_size >= OUT_FULL) ? 1 : 0;

    k_prep<<<2080, 256>>>(z_e, w);
    k_argmax<<<NTOK, AT>>>(gum, w, out, write_extras);
    k_out<<<1024, 256>>>(z_e, w, out, write_extras);
}

// round 9
// speedup vs baseline: 1.5228x; 1.0862x over previous
#include <cuda_runtime.h>
#include <math.h>

#define KCODES   8192
#define DIM      256
#define NTOK     8192       // B*H*W
#define HWSZ     1024
#define ZQ_ELEMS 2097152
#define OUT_FULL (ZQ_ELEMS + 2 + NTOK)
#define CAP      256

static __device__ float    g_flat[NTOK * DIM];   // z_e transposed to [N, D]
static __device__ float    g_w2[KCODES];
static __device__ unsigned g_wmax2_bits;         // monotone max, idempotent across replays
static __device__ int      g_idx[NTOK];
static __device__ int      g_hist[KCODES];
static __device__ double   g_loss;
static __device__ unsigned g_done;

// == Kernel A: transpose (64d x 64hw tiles, 128b both ways) + norms + zeroing ==
__global__ void __launch_bounds__(256) k_prep(const float* __restrict__ ze,
                                              const float* __restrict__ w) {
    int blk = blockIdx.x, t = threadIdx.x;
    if (blk < 512) {
        // transpose z_e [B,D,HW] -> g_flat [B*HW, D]; tile = 64 d x 64 hw
        __shared__ float tile[64][65];
        int b = blk >> 6, rem = blk & 63;
        int d0  = (rem >> 4) << 6;    // 4 d-tiles
        int hw0 = (rem & 15) << 6;    // 16 hw-tiles
        int tx4 = t & 15, ty = t >> 4;
        // load: each thread 4x LDG.128 (4 consecutive hw), rows d = ty + 16*i
#pragma unroll
        for (int i = 0; i < 4; i++) {
            int d = ty + i * 16;
            float4 v = __ldg((const float4*)&ze[(size_t)(b * DIM + d0 + d) * HWSZ + hw0 + tx4 * 4]);
            tile[d][tx4 * 4 + 0] = v.x;
            tile[d][tx4 * 4 + 1] = v.y;
            tile[d][tx4 * 4 + 2] = v.z;
            tile[d][tx4 * 4 + 3] = v.w;
        }
        __syncthreads();
        // store: each thread 4x STG.128 (4 consecutive d for one token)
        int dg = t & 15, tb = t >> 4;
#pragma unroll
        for (int i = 0; i < 4; i++) {
            int tok = tb + i * 16;
            float4 o;
            o.x = tile[dg * 4 + 0][tok];
            o.y = tile[dg * 4 + 1][tok];
            o.z = tile[dg * 4 + 2][tok];
            o.w = tile[dg * 4 + 3][tok];
            *(float4*)&g_flat[(size_t)(b * HWSZ + hw0 + tok) * DIM + d0 + dg * 4] = o;
        }
    } else if (blk < 1536) {
        // |w_k|^2 (one warp per row) + global max
        int row  = ((blk - 512) << 3) | (t >> 5);
        int lane = t & 31;
        const float4* p = (const float4*)(w + (size_t)row * DIM);
        float s = 0.f;
#pragma unroll
        for (int j = 0; j < 2; j++) {
            float4 v = __ldg(p + lane * 2 + j);
            s += v.x * v.x + v.y * v.y + v.z * v.z + v.w * v.w;
        }
#pragma unroll
        for (int o = 16; o; o >>= 1) s += __shfl_xor_sync(0xffffffffu, s, o);
        if (lane == 0) {
            g_w2[row] = s;
            atomicMax(&g_wmax2_bits, __float_as_uint(s));
        }
    } else {
        int i = ((blk - 1536) << 8) | t;
        g_hist[i] = 0;
        if (i == 0) { g_loss = 0.0; g_done = 0u; }
    }
}

// ============ Kernel B: argmax(gumbel + 2 z.w - |w|^2) via bounded pruning ====
__global__ void __launch_bounds__(256, 6) k_argmax(const float* __restrict__ gum,
                                                   const float* __restrict__ w,
                                                   float* __restrict__ out,
                                                   int write_extras) {
    const int n = blockIdx.x;
    const int t = threadIdx.x;
    const int lane = t & 31, wrp = t >> 5;
    __shared__ float sh_z[DIM];
    __shared__ int   sh_cand[CAP];
    __shared__ float sh_cg[CAP];
    __shared__ int   sh_cnt;
    __shared__ float sh_red[8];
    __shared__ float sh_bv[8];
    __shared__ int   sh_bk[8];

    // token's z row + |z|^2
    float zv = g_flat[n * DIM + t];
    sh_z[t] = zv;
    if (t == 0) sh_cnt = 0;
    float s = zv * zv;
#pragma unroll
    for (int o = 16; o; o >>= 1) s += __shfl_xor_sync(0xffffffffu, s, o);
    if (lane == 0) sh_red[wrp] = s;
    __syncthreads();
    float zn2 = 0.f;
#pragma unroll
    for (int i = 0; i < 8; i++) zn2 += sh_red[i];
    float wmax2 = __uint_as_float(g_wmax2_bits);
    float delta = 4.f * sqrtf(zn2) * sqrtf(wmax2) + wmax2 + 1e-5f;
    __syncthreads();

    // single streaming pass over the gumbel row; keep 32 values in registers
    const float4* row4 = (const float4*)(gum + (size_t)n * KCODES);
    float4 vv[8];
#pragma unroll
    for (int j = 0; j < 8; j++) vv[j] = __ldcs(row4 + t + j * 256);
    float m = -INFINITY;
#pragma unroll
    for (int j = 0; j < 8; j++) {
        float4 v = vv[j];
        m = fmaxf(m, fmaxf(fmaxf(v.x, v.y), fmaxf(v.z, v.w)));
    }
#pragma unroll
    for (int o = 16; o; o >>= 1) m = fmaxf(m, __shfl_xor_sync(0xffffffffu, m, o));
    if (lane == 0) sh_red[wrp] = m;
    __syncthreads();
    float gmax = sh_red[0];
#pragma unroll
    for (int i = 1; i < 8; i++) gmax = fmaxf(gmax, sh_red[i]);

    // collect candidates (index + gumbel value) from registers
    float thresh = gmax - delta;
#pragma unroll
    for (int j = 0; j < 8; j++) {
        float4 v = vv[j];
        int kb = (t + j * 256) << 2;
        if (v.x >= thresh) { int p = atomicAdd(&sh_cnt, 1); if (p < CAP) { sh_cand[p] = kb;     sh_cg[p] = v.x; } }
        if (v.y >= thresh) { int p = atomicAdd(&sh_cnt, 1); if (p < CAP) { sh_cand[p] = kb + 1; sh_cg[p] = v.y; } }
        if (v.z >= thresh) { int p = atomicAdd(&sh_cnt, 1); if (p < CAP) { sh_cand[p] = kb + 2; sh_cg[p] = v.z; } }
        if (v.w >= thresh) { int p = atomicAdd(&sh_cnt, 1); if (p < CAP) { sh_cand[p] = kb + 3; sh_cg[p] = v.w; } }
    }
    __syncthreads();
    int cnt = sh_cnt;
    int best_k = -1;

    if (cnt == 1) {
        best_k = sh_cand[0];                         // ~87% of tokens
    } else if (cnt <= CAP) {
        // warp-parallel candidate scoring: warp handles candidates wrp, wrp+8, ...
        float bv = -INFINITY; int bk = KCODES;
        for (int c = wrp; c < cnt; c += 8) {
            int k = sh_cand[c];
            const float4* wr = (const float4*)(w + (size_t)k * DIM);
            float dot = 0.f;
#pragma unroll
            for (int j = 0; j < 2; j++) {
                float4 a = __ldg(wr + lane * 2 + j);
                int db = lane * 8 + j * 4;
                dot += a.x * sh_z[db] + a.y * sh_z[db + 1] + a.z * sh_z[db + 2] + a.w * sh_z[db + 3];
            }
#pragma unroll
            for (int o = 16; o; o >>= 1) dot += __shfl_xor_sync(0xffffffffu, dot, o);
            float sc = sh_cg[c] + 2.f * dot - g_w2[k];
            if (sc > bv || (sc == bv && k < bk)) { bv = sc; bk = k; }
        }
        if (lane == 0) { sh_bv[wrp] = bv; sh_bk[wrp] = bk; }
        __syncthreads();
        if (t == 0) {
            float fb = -INFINITY; int fk = KCODES;
#pragma unroll
            for (int i = 0; i < 8; i++) {
                float v = sh_bv[i]; int k = sh_bk[i];
                if (v > fb || (v == fb && k < fk)) { fb = v; fk = k; }
            }
            best_k = fk;
        }
    } else {
        // statistically unreachable safety net: exact full scan
        float bs = -INFINITY; int bk = KCODES;
        for (int k = t; k < KCODES; k += 256) {
            float dot = 0.f;
            for (int d = 0; d < DIM; d++) dot += sh_z[d] * w[(size_t)k * DIM + d];
            float sc = __ldg(&gum[(size_t)n * KCODES + k]) + 2.f * dot - g_w2[k];
            if (sc > bs || (sc == bs && k < bk)) { bs = sc; bk = k; }
        }
        __syncthreads();
        sh_cg[t] = bs; sh_cand[t] = bk;
        __syncthreads();
        for (int off = 128; off; off >>= 1) {
            if (t < off) {
                float ov = sh_cg[t + off]; int ok = sh_cand[t + off];
                if (ov > sh_cg[t] || (ov == sh_cg[t] && ok < sh_cand[t])) { sh_cg[t] = ov; sh_cand[t] = ok; }
            }
            __syncthreads();
        }
        best_k = sh_cand[0];
    }

    if (t == 0) {
        g_idx[n] = best_k;
        atomicAdd(&g_hist[best_k], 1);
        if (write_extras) out[ZQ_ELEMS + 2 + n] = (float)best_k;
    }
}

// ==== Kernel C: coalesced gather + STE write + loss + (last block) scalars ====
__global__ void __launch_bounds__(256) k_out(const float* __restrict__ ze,
                                             const float* __restrict__ w,
                                             float* __restrict__ out,
                                             int write_extras) {
    __shared__ float tile[32][33];
    __shared__ int   kk[32];
    __shared__ float sr[8];
    __shared__ int   s_last;
    int blk = blockIdx.x, t = threadIdx.x;
    int tx = t & 31, ty = t >> 5;
    int b = blk >> 8, rem = blk & 255;
    int d0 = (rem >> 5) << 5;
    int hw0 = (rem & 31) << 5;

    if (t < 32) kk[t] = g_idx[b * HWSZ + hw0 + t];
    __syncthreads();
#pragma unroll
    for (int i = 0; i < 4; i++) {
        int tok = ty + i * 8;
        tile[tok][tx] = __ldg(&w[(size_t)kk[tok] * DIM + d0 + tx]);
    }
    __syncthreads();

    float acc = 0.f;
#pragma unroll
    for (int i = 0; i < 4; i++) {
        int dd = ty + i * 8;
        size_t gi = (size_t)(b * DIM + d0 + dd) * HWSZ + hw0 + tx;  // NCHW, coalesced
        float zq  = tile[tx][dd];
        float zev = ze[gi];
        float df  = zq - zev;
        out[gi]   = zev + df;
        acc += df * df;
    }
#pragma unroll
    for (int o = 16; o; o >>= 1) acc += __shfl_xor_sync(0xffffffffu, acc, o);
    if ((t & 31) == 0) sr[t >> 5] = acc;
    __syncthreads();
    if (t == 0) {
        float tot = 0.f;
#pragma unroll
        for (int q = 0; q < 8; q++) tot += sr[q];
        atomicAdd(&g_loss, (double)tot);
        __threadfence();
        unsigned old = atomicAdd(&g_done, 1u);
        s_last = (old == gridDim.x - 1) ? 1 : 0;
    }
    __syncthreads();

    if (s_last && write_extras) {
        double accp = 0.0;
        for (int k = t; k < KCODES; k += 256) {
            float p = (float)g_hist[k] * (1.0f / (float)NTOK);
            accp += (double)(p * logf(p + 1e-10f));
        }
#pragma unroll
        for (int o = 16; o; o >>= 1) accp += __shfl_xor_sync(0xffffffffu, accp, o);
        __shared__ double dr[8];
        if ((t & 31) == 0) dr[t >> 5] = accp;
        __syncthreads();
        if (t == 0) {
            double tot = 0.0;
#pragma unroll
            for (int q = 0; q < 8; q++) tot += dr[q];
            double loss = *((volatile double*)&g_loss);
            out[ZQ_ELEMS]     = (float)(1.25 * loss / (double)ZQ_ELEMS);
            out[ZQ_ELEMS + 1] = (float)exp(-tot);
        }
    }
}

extern "C" void kernel_launch(void* const* d_in, const int* in_sizes, int n_in,
                              void* d_out, int out_size) {
    const float* gum = nullptr;
    const float* small[2] = {nullptr, nullptr};
    int ns = 0;
    for (int i = 0; i < n_in; i++) {
        if (in_sizes[i] == KCODES * NTOK) gum = (const float*)d_in[i];
        else if (ns < 2) small[ns++] = (const float*)d_in[i];
    }
    const float* z_e = small[0];
    const float* w   = small[1];
    float* out = (float*)d_out;
    int write_extras = (out_size >= OUT_FULL) ? 1 : 0;

    k_prep<<<1568, 256>>>(z_e, w);
    k_argmax<<<NTOK, 256>>>(gum, w, out, write_extras);
    k_out<<<2048, 256>>>(z_e, w, out, write_extras);
}